// round 3
// baseline (speedup 1.0000x reference)
#include <cuda_runtime.h>

// PCLSTM: B=20, C=395, H=10, T=8192.
// Phase 1 (pre_gemm): pre[b][t][h][g] = (x·Wx + y_prev·Wy + bias), with activation
//   log2e scalings folded in (gates f,i,o scaled by -log2e for exp-sigmoid; gate u
//   scaled by 2*log2e for exp-tanh). Packed f32x2 FMAs, weights duplicated in smem.
// Phase 2 (lstm_rec): 20 single-warp blocks (one per batch, one per SM), lane j owns
//   hidden unit j. h exchanged via shfl; pre prefetched via float4 one 4-step group
//   ahead; h written as float4 every 4 steps.
// c0 = b_init (W_init is mathematically unused).

#define Bk 20
#define Ck 395
#define Hk 10
#define Tk 8192
#define GIN 800
#define CHUNK 64

typedef unsigned long long ull;

// pre buffer: [b][t][h] as float4 (x=f,y=i,z=u,w=o), + pad for harmless over-prefetch
__device__ __align__(16) float4 g_pre[(size_t)Bk * Tk * 10 + 256];

__device__ __forceinline__ ull pack2(float a, float b) {
    ull r; asm("mov.b64 %0, {%1,%2};" : "=l"(r) : "f"(a), "f"(b)); return r;
}
__device__ __forceinline__ void unpack2(ull v, float& a, float& b) {
    asm("mov.b64 {%0,%1}, %2;" : "=f"(a), "=f"(b) : "l"(v));
}
__device__ __forceinline__ void ffma2(ull& d, ull a, ull b) {
    asm("fma.rn.f32x2 %0, %1, %2, %0;" : "+l"(d) : "l"(a), "l"(b));
}
__device__ __forceinline__ float ex2f(float x) {
    float r; asm("ex2.approx.f32 %0, %1;" : "=f"(r) : "f"(x)); return r;
}
__device__ __forceinline__ float rcpf(float x) {
    float r; asm("rcp.approx.f32 %0, %1;" : "=f"(r) : "f"(x)); return r;
}

#define NL2E  (-1.4426950408889634f)   // -log2(e):  sigmoid(z) = rcp(1 + ex2(NL2E*z))
#define P2L2E ( 2.8853900817779268f)   // 2*log2(e): tanh(z)    = 1 - 2*rcp(1 + ex2(P2L2E*z))

// ---------------------------------------------------------------------------
// Phase 1: time-parallel gate pre-activations
// grid (Tk/256, Bk), 128 threads; each thread owns 2 consecutive t.
// ---------------------------------------------------------------------------
__global__ __launch_bounds__(128) void pre_gemm(
    const float* __restrict__ x, const float* __restrict__ y,
    const float* __restrict__ Wf, const float* __restrict__ bf,
    const float* __restrict__ Wi, const float* __restrict__ bi,
    const float* __restrict__ Wu, const float* __restrict__ bu,
    const float* __restrict__ Wo, const float* __restrict__ bo)
{
    __shared__ __align__(16) ull sWx[CHUNK * 40];
    __shared__ __align__(16) ull sWy[CHUNK * 40];

    const int tid = threadIdx.x;
    const int b = blockIdx.y;
    const int t = blockIdx.x * 256 + tid * 2;

    ull acc[40];
    #pragma unroll
    for (int h = 0; h < Hk; ++h) {
        acc[h]      = pack2(bf[h], bf[h]);
        acc[10 + h] = pack2(bi[h], bi[h]);
        acc[20 + h] = pack2(bu[h], bu[h]);
        acc[30 + h] = pack2(bo[h], bo[h]);
    }

    for (int c0 = 0; c0 < Ck; c0 += CHUNK) {
        const int clen = min(CHUNK, Ck - c0);
        __syncthreads();
        for (int idx = tid; idx < clen * 40; idx += 128) {
            int cl = idx / 40;
            int gh = idx - cl * 40;
            int g = gh / 10;
            int h = gh - g * 10;
            const float* Wgp = (g == 0) ? Wf : ((g == 1) ? Wi : ((g == 2) ? Wu : Wo));
            int col = c0 + cl;
            float wx  = Wgp[h * GIN + col];
            float wyv = Wgp[h * GIN + (Ck + Hk) + col];
            sWx[cl * 40 + gh] = pack2(wx, wx);
            sWy[cl * 40 + gh] = pack2(wyv, wyv);
        }
        __syncthreads();

        const float* xp = x + ((size_t)(b * Ck + c0)) * Tk + t;
        const float* yp = y + ((size_t)(b * Ck + c0)) * Tk + t;
        for (int cl = 0; cl < clen; ++cl) {
            float2 xv = *(const float2*)xp;
            float ya = (t > 0) ? yp[-1] : 0.0f;   // y_prev[t]   = y[t-1]
            float yb = yp[0];                     // y_prev[t+1] = y[t]
            ull X2 = pack2(xv.x, xv.y);
            ull Y2 = pack2(ya, yb);
            const ulonglong2* wx2 = (const ulonglong2*)&sWx[cl * 40];
            const ulonglong2* wy2 = (const ulonglong2*)&sWy[cl * 40];
            #pragma unroll
            for (int q = 0; q < 20; ++q) {
                ulonglong2 wa = wx2[q];
                ffma2(acc[2 * q],     X2, wa.x);
                ffma2(acc[2 * q + 1], X2, wa.y);
            }
            #pragma unroll
            for (int q = 0; q < 20; ++q) {
                ulonglong2 wb = wy2[q];
                ffma2(acc[2 * q],     Y2, wb.x);
                ffma2(acc[2 * q + 1], Y2, wb.y);
            }
            xp += Tk; yp += Tk;
        }
    }

    // Epilogue: apply log2e folding, store [t][h][gate] as float4
    float4* outp = g_pre + ((size_t)b * Tk + t) * 10;
    #pragma unroll
    for (int h = 0; h < Hk; ++h) {
        float f0, f1, i0, i1, u0, u1, o0, o1;
        unpack2(acc[h],      f0, f1);
        unpack2(acc[10 + h], i0, i1);
        unpack2(acc[20 + h], u0, u1);
        unpack2(acc[30 + h], o0, o1);
        outp[h]      = make_float4(NL2E * f0, NL2E * i0, P2L2E * u0, NL2E * o0);
        outp[10 + h] = make_float4(NL2E * f1, NL2E * i1, P2L2E * u1, NL2E * o1);
    }
}

// ---------------------------------------------------------------------------
// Phase 2: sequential recurrence. 20 blocks x 32 threads (1 warp / batch / SM).
// ---------------------------------------------------------------------------
__device__ __forceinline__ void lstm_step(
    float4 pf, float& hval, float& cval,
    const float* whf, const float* whi, const float* whu, const float* who)
{
    float zf = pf.x, zi = pf.y, zu = pf.z, zo = pf.w;
    float zf2 = 0.f, zi2 = 0.f, zu2 = 0.f, zo2 = 0.f;
    float hk[10];
    #pragma unroll
    for (int k = 0; k < 10; ++k) hk[k] = __shfl_sync(0xffffffffu, hval, k);
    #pragma unroll
    for (int k = 0; k < 10; k += 2) {
        zf  = fmaf(hk[k],     whf[k],     zf);
        zf2 = fmaf(hk[k + 1], whf[k + 1], zf2);
        zi  = fmaf(hk[k],     whi[k],     zi);
        zi2 = fmaf(hk[k + 1], whi[k + 1], zi2);
        zu  = fmaf(hk[k],     whu[k],     zu);
        zu2 = fmaf(hk[k + 1], whu[k + 1], zu2);
        zo  = fmaf(hk[k],     who[k],     zo);
        zo2 = fmaf(hk[k + 1], who[k + 1], zo2);
    }
    zf += zf2; zi += zi2; zu += zu2; zo += zo2;
    // zf/zi/zo are already -log2e * z ; zu is already 2*log2e * z
    float f = rcpf(1.0f + ex2f(zf));
    float i = rcpf(1.0f + ex2f(zi));
    float g = fmaf(-2.0f, rcpf(1.0f + ex2f(zu)), 1.0f);
    float o = rcpf(1.0f + ex2f(zo));
    cval = fmaf(cval, f, i * g);
    float tc = fmaf(-2.0f, rcpf(1.0f + ex2f(cval * P2L2E)), 1.0f);
    hval = o * tc;
}

__global__ __launch_bounds__(32) void lstm_rec(
    const float* __restrict__ Wf, const float* __restrict__ Wi,
    const float* __restrict__ Wu, const float* __restrict__ Wo,
    const float* __restrict__ b_init, float* __restrict__ out)
{
    const int b = blockIdx.x;
    const int lane = threadIdx.x;
    const int j = lane % 10;   // lanes >=10 mirror (harmless, keeps warp converged)

    float whf[10], whi[10], whu[10], who[10];
    #pragma unroll
    for (int k = 0; k < 10; ++k) {
        whf[k] = NL2E  * Wf[j * GIN + Ck + k];
        whi[k] = NL2E  * Wi[j * GIN + Ck + k];
        whu[k] = P2L2E * Wu[j * GIN + Ck + k];
        who[k] = NL2E  * Wo[j * GIN + Ck + k];
    }

    float hval = 0.0f;
    float cval = b_init[j];

    const float4* pp = g_pre + (size_t)b * Tk * 10 + j;
    float4 cur0 = pp[0],  cur1 = pp[10], cur2 = pp[20], cur3 = pp[30];
    float4 nx0  = pp[40], nx1  = pp[50], nx2  = pp[60], nx3  = pp[70];

    float* op = out + ((size_t)b * Hk + j) * Tk;

    #pragma unroll 1
    for (int t0 = 0; t0 < Tk; t0 += 4) {
        float ho0, ho1, ho2, ho3;
        lstm_step(cur0, hval, cval, whf, whi, whu, who); ho0 = hval;
        lstm_step(cur1, hval, cval, whf, whi, whu, who); ho1 = hval;
        lstm_step(cur2, hval, cval, whf, whi, whu, who); ho2 = hval;
        lstm_step(cur3, hval, cval, whf, whi, whu, who); ho3 = hval;

        if (lane < 10) *(float4*)(op + t0) = make_float4(ho0, ho1, ho2, ho3);

        cur0 = nx0; cur1 = nx1; cur2 = nx2; cur3 = nx3;
        const float4* np = pp + (size_t)(t0 + 8) * 10;   // pad covers overrun
        nx0 = np[0]; nx1 = np[10]; nx2 = np[20]; nx3 = np[30];
    }

    if (lane < 10) out[(size_t)Bk * Hk * Tk + b * Hk + j] = cval;   // cT
}

// ---------------------------------------------------------------------------
extern "C" void kernel_launch(void* const* d_in, const int* in_sizes, int n_in,
                              void* d_out, int out_size)
{
    const float* x      = (const float*)d_in[0];
    const float* y      = (const float*)d_in[1];
    const float* Wf     = (const float*)d_in[2];
    const float* bf     = (const float*)d_in[3];
    const float* Wi     = (const float*)d_in[4];
    const float* bi     = (const float*)d_in[5];
    const float* Wu     = (const float*)d_in[6];
    const float* bu     = (const float*)d_in[7];
    const float* Wo     = (const float*)d_in[8];
    const float* bo     = (const float*)d_in[9];
    // d_in[10] = W_init: unused (c0 = 0 @ W_init.T + b_init == b_init)
    const float* b_init = (const float*)d_in[11];
    float* out = (float*)d_out;
    (void)in_sizes; (void)n_in; (void)out_size;

    dim3 grid(Tk / 256, Bk);
    pre_gemm<<<grid, 128>>>(x, y, Wf, bf, Wi, bi, Wu, bu, Wo, bo);
    lstm_rec<<<Bk, 32>>>(Wf, Wi, Wu, Wo, b_init, out);
}

// round 4
// speedup vs baseline: 1.7316x; 1.7316x over previous
#include <cuda_runtime.h>

// PCLSTM: B=20, C=395, H=10, T=8192.
// Fused single kernel: blocks [0,20) run the sequential recurrence (1 warp each),
// blocks [20,660) compute gate pre-activations for one (chunk-of-256-t, batch)
// tile and publish per-chunk ready flags. Recurrence warps chase the flags.
// c0 = b_init (W_init mathematically unused).

#define Bk 20
#define Ck 395
#define Hk 10
#define Tk 8192
#define GIN 800
#define CHUNK 32
#define NCHUNKS 32     // Tk / 256
#define TCH 256

typedef unsigned long long ull;

// pre buffer: [b][t][h] float4 (x=f,y=i,z=u,w=o pre-scaled), + pad for prefetch overrun
__device__ __align__(16) float4 g_pre[(size_t)Bk * Tk * 10 + 256];
__device__ int g_ready[NCHUNKS];

__device__ __forceinline__ ull pack2(float a, float b) {
    ull r; asm("mov.b64 %0, {%1,%2};" : "=l"(r) : "f"(a), "f"(b)); return r;
}
__device__ __forceinline__ void unpack2(ull v, float& a, float& b) {
    asm("mov.b64 {%0,%1}, %2;" : "=f"(a), "=f"(b) : "l"(v));
}
__device__ __forceinline__ void ffma2(ull& d, ull a, ull b) {
    asm("fma.rn.f32x2 %0, %1, %2, %0;" : "+l"(d) : "l"(a), "l"(b));
}
__device__ __forceinline__ float ex2f(float x) {
    float r; asm("ex2.approx.f32 %0, %1;" : "=f"(r) : "f"(x)); return r;
}
__device__ __forceinline__ float rcpf(float x) {
    float r; asm("rcp.approx.f32 %0, %1;" : "=f"(r) : "f"(x)); return r;
}
__device__ __forceinline__ int ld_acq(const int* p) {
    int v; asm volatile("ld.acquire.gpu.b32 %0, [%1];" : "=r"(v) : "l"(p) : "memory");
    return v;
}

#define NL2E  (-1.4426950408889634f)   // -log2(e):  sigmoid(z) = rcp(1 + ex2(NL2E*z))
#define P2L2E ( 2.8853900817779268f)   // 2*log2(e): tanh(z)    = 1 - 2*rcp(1 + ex2(P2L2E*z))

__global__ void zero_flags() {
    if (threadIdx.x < NCHUNKS) g_ready[threadIdx.x] = 0;
}

// ---------------------------------------------------------------------------
// One LSTM step. Lanes 0-9 (and mirror 20-29): owner of unit j, compute f,i,u.
// Lanes 10-19: compute o for unit j=lane-10; shipped to owner via shfl (off-chain).
// pf is pre-scaled: x=NL2E*zf, y=NL2E*zi, z=P2L2E*zu, w=NL2E*zo.
// ---------------------------------------------------------------------------
__device__ __forceinline__ float step_fn(
    float4 pf, bool owner, int osrc, float& hval, float& cval,
    const ull* wA, const ull* wB, const ull* wC)
{
    float hk[10];
    #pragma unroll
    for (int k = 0; k < 10; ++k) hk[k] = __shfl_sync(0xffffffffu, hval, k);
    ull hp[5];
    #pragma unroll
    for (int q = 0; q < 5; ++q) hp[q] = pack2(hk[2 * q], hk[2 * q + 1]);

    float p0 = owner ? pf.x : pf.w;
    ull A  = pack2(p0,   0.0f);
    ull Bv = pack2(pf.y, 0.0f);
    ull Cv = pack2(pf.z, 0.0f);
    #pragma unroll
    for (int q = 0; q < 5; ++q) {
        ffma2(A,  hp[q], wA[q]);
        ffma2(Bv, hp[q], wB[q]);
        ffma2(Cv, hp[q], wC[q]);
    }
    float alo, ahi, blo, bhi, clo, chi;
    unpack2(A, alo, ahi); unpack2(Bv, blo, bhi); unpack2(Cv, clo, chi);
    float z0 = alo + ahi, z1 = blo + bhi, z2 = clo + chi;

    // slot0: sigmoid -> f (owner) / o (o-lane)
    float e0 = ex2f(z0);
    float r0 = rcpf(1.0f + e0);
    float osh = __shfl_sync(0xffffffffu, r0, osrc);   // o arrives off-chain

    // i*g = (b-1) * rcp((1+a)(1+b)),  a = e^{-zi}, b = e^{2*zu}
    float a1 = ex2f(z1);
    float bb = ex2f(z2);
    float bp = bb + 1.0f;
    float ig = (bb - 1.0f) * rcpf(fmaf(a1, bp, bp));

    cval = fmaf(cval, r0, ig);

    // h = o * tanh(c) = o - 2*o*rcp(1 + e^{2c})   (overflow-safe)
    float d  = ex2f(cval * P2L2E);
    float rt = rcpf(1.0f + d);
    hval = fmaf(-2.0f * osh, rt, osh);
    return hval;
}

__device__ __forceinline__ void spin_chunk(int k) {
    #pragma unroll 1
    while (ld_acq(&g_ready[k]) < Bk) { }
}

// ---------------------------------------------------------------------------
__global__ __launch_bounds__(128) void pclstm_fused(
    const float* __restrict__ x, const float* __restrict__ y,
    const float* __restrict__ Wf, const float* __restrict__ bf,
    const float* __restrict__ Wi, const float* __restrict__ bi,
    const float* __restrict__ Wu, const float* __restrict__ bu,
    const float* __restrict__ Wo, const float* __restrict__ bo,
    const float* __restrict__ b_init, float* __restrict__ out)
{
    __shared__ __align__(16) ull sWx[CHUNK * 40];
    __shared__ __align__(16) ull sWy[CHUNK * 40];

    const int tid = threadIdx.x;
    const int bx  = blockIdx.x;

    if (bx < Bk) {
        // ================= recurrence role (1 warp per batch) =================
        if (tid >= 32) return;
        const int lane = tid;
        const int j = lane % 10;
        const bool owner = (lane < 10) || (lane >= 20);
        const int osrc = 10 + j;

        const float* WA = owner ? Wf : Wo;
        float wa[10], wb[10], wc[10];
        #pragma unroll
        for (int k = 0; k < 10; ++k) {
            wa[k] = NL2E * WA[j * GIN + Ck + k];
            wb[k] = owner ? (NL2E  * Wi[j * GIN + Ck + k]) : 0.0f;
            wc[k] = owner ? (P2L2E * Wu[j * GIN + Ck + k]) : 0.0f;
        }
        ull wA2[5], wB2[5], wC2[5];
        #pragma unroll
        for (int q = 0; q < 5; ++q) {
            wA2[q] = pack2(wa[2 * q], wa[2 * q + 1]);
            wB2[q] = pack2(wb[2 * q], wb[2 * q + 1]);
            wC2[q] = pack2(wc[2 * q], wc[2 * q + 1]);
        }

        float hval = 0.0f;
        float cval = b_init[j];

        const float4* pp = g_pre + (size_t)bx * Tk * 10 + j;
        float* op = out + ((size_t)bx * Hk + j) * Tk;

        spin_chunk(0);
        float4 cur0 = pp[0],  cur1 = pp[10], cur2 = pp[20], cur3 = pp[30];
        float4 nx0  = pp[40], nx1  = pp[50], nx2  = pp[60], nx3  = pp[70];

        #pragma unroll 1
        for (int kc = 0; kc < NCHUNKS; ++kc) {
            spin_chunk(kc < NCHUNKS - 1 ? kc + 1 : NCHUNKS - 1);
            const int tend = kc * TCH + TCH;
            #pragma unroll 1
            for (int t0 = kc * TCH; t0 < tend; t0 += 4) {
                float h0 = step_fn(cur0, owner, osrc, hval, cval, wA2, wB2, wC2);
                float h1 = step_fn(cur1, owner, osrc, hval, cval, wA2, wB2, wC2);
                float h2 = step_fn(cur2, owner, osrc, hval, cval, wA2, wB2, wC2);
                float h3 = step_fn(cur3, owner, osrc, hval, cval, wA2, wB2, wC2);

                if (lane < 10) *(float4*)(op + t0) = make_float4(h0, h1, h2, h3);

                cur0 = nx0; cur1 = nx1; cur2 = nx2; cur3 = nx3;
                const float4* np = pp + (size_t)(t0 + 8) * 10;   // pad covers overrun
                nx0 = np[0]; nx1 = np[10]; nx2 = np[20]; nx3 = np[30];
            }
        }
        if (lane < 10) out[(size_t)Bk * Hk * Tk + bx * Hk + j] = cval;
        return;
    }

    // ================= GEMM role: one (chunk, batch) tile =================
    const int g     = bx - Bk;
    const int b     = g % Bk;        // batch varies fastest -> chunk-major completion
    const int chunk = g / Bk;
    const int t     = chunk * TCH + tid * 2;

    ull acc[40];
    #pragma unroll
    for (int h = 0; h < Hk; ++h) {
        acc[h]      = pack2(bf[h], bf[h]);
        acc[10 + h] = pack2(bi[h], bi[h]);
        acc[20 + h] = pack2(bu[h], bu[h]);
        acc[30 + h] = pack2(bo[h], bo[h]);
    }

    for (int c0 = 0; c0 < Ck; c0 += CHUNK) {
        const int clen = min(CHUNK, Ck - c0);
        __syncthreads();
        for (int idx = tid; idx < clen * 40; idx += 128) {
            int cl = idx / 40;
            int gh = idx - cl * 40;
            int gg = gh / 10;
            int h  = gh - gg * 10;
            const float* Wgp = (gg == 0) ? Wf : ((gg == 1) ? Wi : ((gg == 2) ? Wu : Wo));
            int col = c0 + cl;
            float wx  = Wgp[h * GIN + col];
            float wyv = Wgp[h * GIN + (Ck + Hk) + col];
            sWx[cl * 40 + gh] = pack2(wx, wx);
            sWy[cl * 40 + gh] = pack2(wyv, wyv);
        }
        __syncthreads();

        const float* xp = x + ((size_t)(b * Ck + c0)) * Tk + t;
        const float* yp = y + ((size_t)(b * Ck + c0)) * Tk + t;
        for (int cl = 0; cl < clen; ++cl) {
            float2 xv = *(const float2*)xp;
            float ya = (t > 0) ? yp[-1] : 0.0f;   // y_prev[t]   = y[t-1]
            float yb = yp[0];                     // y_prev[t+1] = y[t]
            ull X2 = pack2(xv.x, xv.y);
            ull Y2 = pack2(ya, yb);
            const ulonglong2* wx2 = (const ulonglong2*)&sWx[cl * 40];
            const ulonglong2* wy2 = (const ulonglong2*)&sWy[cl * 40];
            #pragma unroll
            for (int q = 0; q < 20; ++q) {
                ulonglong2 wv = wx2[q];
                ffma2(acc[2 * q],     X2, wv.x);
                ffma2(acc[2 * q + 1], X2, wv.y);
            }
            #pragma unroll
            for (int q = 0; q < 20; ++q) {
                ulonglong2 wv = wy2[q];
                ffma2(acc[2 * q],     Y2, wv.x);
                ffma2(acc[2 * q + 1], Y2, wv.y);
            }
            xp += Tk; yp += Tk;
        }
    }

    // Epilogue: fold activation log2e scalings, store [t][h][gate] as float4
    float4* outp = g_pre + ((size_t)b * Tk + t) * 10;
    #pragma unroll
    for (int h = 0; h < Hk; ++h) {
        float f0, f1, i0, i1, u0, u1, o0, o1;
        unpack2(acc[h],      f0, f1);
        unpack2(acc[10 + h], i0, i1);
        unpack2(acc[20 + h], u0, u1);
        unpack2(acc[30 + h], o0, o1);
        outp[h]      = make_float4(NL2E * f0, NL2E * i0, P2L2E * u0, NL2E * o0);
        outp[10 + h] = make_float4(NL2E * f1, NL2E * i1, P2L2E * u1, NL2E * o1);
    }

    __threadfence();
    __syncthreads();
    if (tid == 0) atomicAdd(&g_ready[chunk], 1);
}

// ---------------------------------------------------------------------------
extern "C" void kernel_launch(void* const* d_in, const int* in_sizes, int n_in,
                              void* d_out, int out_size)
{
    const float* x      = (const float*)d_in[0];
    const float* y      = (const float*)d_in[1];
    const float* Wf     = (const float*)d_in[2];
    const float* bf     = (const float*)d_in[3];
    const float* Wi     = (const float*)d_in[4];
    const float* bi     = (const float*)d_in[5];
    const float* Wu     = (const float*)d_in[6];
    const float* bu     = (const float*)d_in[7];
    const float* Wo     = (const float*)d_in[8];
    const float* bo     = (const float*)d_in[9];
    // d_in[10] = W_init: unused (c0 = 0 @ W_init.T + b_init == b_init)
    const float* b_init = (const float*)d_in[11];
    float* out = (float*)d_out;
    (void)in_sizes; (void)n_in; (void)out_size;

    zero_flags<<<1, 32>>>();
    pclstm_fused<<<Bk + NCHUNKS * Bk, 128>>>(x, y, Wf, bf, Wi, bi, Wu, bu, Wo, bo,
                                             b_init, out);
}

// round 6
// speedup vs baseline: 1.9967x; 1.1531x over previous
#include <cuda_runtime.h>

// PCLSTM: B=20, C=395, H=10, T=8192.
// Fused single kernel: blocks [0,20) run the sequential recurrence (1 warp each),
// blocks [20,660) compute gate pre-activations for one (chunk-of-256-t, batch)
// tile and publish per-chunk ready flags. Recurrence warps chase the flags.
// Activations via tanh.approx.f32:
//   sigmoid(z) = 0.5 + 0.5*tanh(0.5*z)  (0.5*z folded into pre/Wh weights)
//   tanh(z), tanh(c) direct.
// c0 = b_init (W_init mathematically unused).

#define Bk 20
#define Ck 395
#define Hk 10
#define Tk 8192
#define GIN 800
#define CHUNK 32
#define NCHUNKS 32     // Tk / 256
#define TCH 256

typedef unsigned long long ull;

// pre buffer: [b][t][h] float4 (x=.5*zf, y=.5*zi, z=zu, w=.5*zo), + pad for prefetch overrun
__device__ __align__(16) float4 g_pre[(size_t)Bk * Tk * 10 + 256];
__device__ int g_ready[NCHUNKS];

__device__ __forceinline__ ull pack2(float a, float b) {
    ull r; asm("mov.b64 %0, {%1,%2};" : "=l"(r) : "f"(a), "f"(b)); return r;
}
__device__ __forceinline__ void unpack2(ull v, float& a, float& b) {
    asm("mov.b64 {%0,%1}, %2;" : "=f"(a), "=f"(b) : "l"(v));
}
__device__ __forceinline__ void ffma2(ull& d, ull a, ull b) {
    asm("fma.rn.f32x2 %0, %1, %2, %0;" : "+l"(d) : "l"(a), "l"(b));
}
__device__ __forceinline__ float tanhf_a(float x) {
    float r; asm("tanh.approx.f32 %0, %1;" : "=f"(r) : "f"(x)); return r;
}
__device__ __forceinline__ int ld_acq(const int* p) {
    int v; asm volatile("ld.acquire.gpu.b32 %0, [%1];" : "=r"(v) : "l"(p) : "memory");
    return v;
}

__global__ void zero_flags() {
    if (threadIdx.x < NCHUNKS) g_ready[threadIdx.x] = 0;
}

// ---------------------------------------------------------------------------
// One LSTM step. Lanes 0-9 (mirror 20-29): owner of unit j, compute f,i,u + c,h.
// Lanes 10-19: compute o for unit j=lane-10; shipped to owner via shfl (off-chain).
// pf pre-scaled: x=0.5*zf, y=0.5*zi, z=zu, w=0.5*zo. Wh similarly pre-scaled.
// ---------------------------------------------------------------------------
__device__ __forceinline__ float step_fn(
    float4 pf, bool owner, int osrc, float& hval, float& cval,
    const ull* wA, const ull* wB, const ull* wC)
{
    float hk[10];
    #pragma unroll
    for (int k = 0; k < 10; ++k) hk[k] = __shfl_sync(0xffffffffu, hval, k);
    ull hp[5];
    #pragma unroll
    for (int q = 0; q < 5; ++q) hp[q] = pack2(hk[2 * q], hk[2 * q + 1]);

    float p0 = owner ? pf.x : pf.w;
    ull A  = pack2(p0,   0.0f);
    ull Bv = pack2(pf.y, 0.0f);
    ull Cv = pack2(pf.z, 0.0f);
    #pragma unroll
    for (int q = 0; q < 5; ++q) {
        ffma2(A,  hp[q], wA[q]);
        ffma2(Bv, hp[q], wB[q]);
        ffma2(Cv, hp[q], wC[q]);
    }
    float alo, ahi, blo, bhi, clo, chi;
    unpack2(A, alo, ahi); unpack2(Bv, blo, bhi); unpack2(Cv, clo, chi);
    float z0 = alo + ahi, z1 = blo + bhi, z2 = clo + chi;

    // slot0: sigmoid -> f (owner) / o (o-lane)
    float t0 = tanhf_a(z0);
    float r0 = fmaf(0.5f, t0, 0.5f);
    float osh = __shfl_sync(0xffffffffu, r0, osrc);   // o arrives off-chain

    float ti = tanhf_a(z1);
    float tg = tanhf_a(z2);
    float iv = fmaf(0.5f, ti, 0.5f);
    float ig = iv * tg;

    cval = fmaf(cval, r0, ig);
    float tc = tanhf_a(cval);
    hval = osh * tc;
    return hval;
}

__device__ __forceinline__ void spin_chunk(int k) {
    #pragma unroll 1
    while (ld_acq(&g_ready[k]) < Bk) { }
}

// ---------------------------------------------------------------------------
__global__ __launch_bounds__(128) void pclstm_fused(
    const float* __restrict__ x, const float* __restrict__ y,
    const float* __restrict__ Wf, const float* __restrict__ bf,
    const float* __restrict__ Wi, const float* __restrict__ bi,
    const float* __restrict__ Wu, const float* __restrict__ bu,
    const float* __restrict__ Wo, const float* __restrict__ bo,
    const float* __restrict__ b_init, float* __restrict__ out)
{
    __shared__ __align__(16) ull sWx[CHUNK * 40];
    __shared__ __align__(16) ull sWy[CHUNK * 40];

    const int tid = threadIdx.x;
    const int bx  = blockIdx.x;

    if (bx < Bk) {
        // ================= recurrence role (1 warp per batch) =================
        if (tid >= 32) return;
        const int lane = tid;
        const int j = lane % 10;
        const bool owner = (lane < 10) || (lane >= 20);
        const int osrc = 10 + j;

        const float* WA = owner ? Wf : Wo;
        float wa[10], wb[10], wc[10];
        #pragma unroll
        for (int k = 0; k < 10; ++k) {
            wa[k] = 0.5f * WA[j * GIN + Ck + k];
            wb[k] = owner ? (0.5f * Wi[j * GIN + Ck + k]) : 0.0f;
            wc[k] = owner ? Wu[j * GIN + Ck + k] : 0.0f;
        }
        ull wA2[5], wB2[5], wC2[5];
        #pragma unroll
        for (int q = 0; q < 5; ++q) {
            wA2[q] = pack2(wa[2 * q], wa[2 * q + 1]);
            wB2[q] = pack2(wb[2 * q], wb[2 * q + 1]);
            wC2[q] = pack2(wc[2 * q], wc[2 * q + 1]);
        }

        float hval = 0.0f;
        float cval = b_init[j];

        const float4* pp = g_pre + (size_t)bx * Tk * 10 + j;
        float* op = out + ((size_t)bx * Hk + j) * Tk;

        spin_chunk(0);
        float4 cur0 = pp[0],  cur1 = pp[10], cur2 = pp[20], cur3 = pp[30];
        float4 nx0  = pp[40], nx1  = pp[50], nx2  = pp[60], nx3  = pp[70];

        #pragma unroll 1
        for (int kc = 0; kc < NCHUNKS; ++kc) {
            spin_chunk(kc < NCHUNKS - 1 ? kc + 1 : NCHUNKS - 1);
            const int tend = kc * TCH + TCH;
            #pragma unroll 1
            for (int t0 = kc * TCH; t0 < tend; t0 += 4) {
                float h0 = step_fn(cur0, owner, osrc, hval, cval, wA2, wB2, wC2);
                float h1 = step_fn(cur1, owner, osrc, hval, cval, wA2, wB2, wC2);
                float h2 = step_fn(cur2, owner, osrc, hval, cval, wA2, wB2, wC2);
                float h3 = step_fn(cur3, owner, osrc, hval, cval, wA2, wB2, wC2);

                if (lane < 10) *(float4*)(op + t0) = make_float4(h0, h1, h2, h3);

                cur0 = nx0; cur1 = nx1; cur2 = nx2; cur3 = nx3;
                const float4* np = pp + (size_t)(t0 + 8) * 10;   // pad covers overrun
                nx0 = np[0]; nx1 = np[10]; nx2 = np[20]; nx3 = np[30];
            }
        }
        if (lane < 10) out[(size_t)Bk * Hk * Tk + bx * Hk + j] = cval;
        return;
    }

    // ================= GEMM role: one (chunk, batch) tile =================
    const int g     = bx - Bk;
    const int b     = g % Bk;        // batch varies fastest -> chunk-major completion
    const int chunk = g / Bk;
    const int t     = chunk * TCH + tid * 2;

    ull acc[40];
    #pragma unroll
    for (int h = 0; h < Hk; ++h) {
        acc[h]      = pack2(bf[h], bf[h]);
        acc[10 + h] = pack2(bi[h], bi[h]);
        acc[20 + h] = pack2(bu[h], bu[h]);
        acc[30 + h] = pack2(bo[h], bo[h]);
    }

    for (int c0 = 0; c0 < Ck; c0 += CHUNK) {
        const int clen = min(CHUNK, Ck - c0);
        __syncthreads();
        for (int idx = tid; idx < clen * 40; idx += 128) {
            int cl = idx / 40;
            int gh = idx - cl * 40;
            int gg = gh / 10;
            int h  = gh - gg * 10;
            const float* Wgp = (gg == 0) ? Wf : ((gg == 1) ? Wi : ((gg == 2) ? Wu : Wo));
            int col = c0 + cl;
            float wx  = Wgp[h * GIN + col];
            float wyv = Wgp[h * GIN + (Ck + Hk) + col];
            sWx[cl * 40 + gh] = pack2(wx, wx);
            sWy[cl * 40 + gh] = pack2(wyv, wyv);
        }
        __syncthreads();

        const float* xp = x + ((size_t)(b * Ck + c0)) * Tk + t;
        const float* yp = y + ((size_t)(b * Ck + c0)) * Tk + t;
        for (int cl = 0; cl < clen; ++cl) {
            float2 xv = *(const float2*)xp;
            float ya = (t > 0) ? yp[-1] : 0.0f;   // y_prev[t]   = y[t-1]
            float yb = yp[0];                     // y_prev[t+1] = y[t]
            ull X2 = pack2(xv.x, xv.y);
            ull Y2 = pack2(ya, yb);
            const ulonglong2* wx2 = (const ulonglong2*)&sWx[cl * 40];
            const ulonglong2* wy2 = (const ulonglong2*)&sWy[cl * 40];
            #pragma unroll
            for (int q = 0; q < 20; ++q) {
                ulonglong2 wv = wx2[q];
                ffma2(acc[2 * q],     X2, wv.x);
                ffma2(acc[2 * q + 1], X2, wv.y);
            }
            #pragma unroll
            for (int q = 0; q < 20; ++q) {
                ulonglong2 wv = wy2[q];
                ffma2(acc[2 * q],     Y2, wv.x);
                ffma2(acc[2 * q + 1], Y2, wv.y);
            }
            xp += Tk; yp += Tk;
        }
    }

    // Epilogue: fold sigmoid 0.5 scaling (f,i,o); u unscaled. Store [t][h][gate] float4.
    float4* outp = g_pre + ((size_t)b * Tk + t) * 10;
    #pragma unroll
    for (int h = 0; h < Hk; ++h) {
        float f0, f1, i0, i1, u0, u1, o0, o1;
        unpack2(acc[h],      f0, f1);
        unpack2(acc[10 + h], i0, i1);
        unpack2(acc[20 + h], u0, u1);
        unpack2(acc[30 + h], o0, o1);
        outp[h]      = make_float4(0.5f * f0, 0.5f * i0, u0, 0.5f * o0);
        outp[10 + h] = make_float4(0.5f * f1, 0.5f * i1, u1, 0.5f * o1);
    }

    __threadfence();
    __syncthreads();
    if (tid == 0) atomicAdd(&g_ready[chunk], 1);
}

// ---------------------------------------------------------------------------
extern "C" void kernel_launch(void* const* d_in, const int* in_sizes, int n_in,
                              void* d_out, int out_size)
{
    const float* x      = (const float*)d_in[0];
    const float* y      = (const float*)d_in[1];
    const float* Wf     = (const float*)d_in[2];
    const float* bf     = (const float*)d_in[3];
    const float* Wi     = (const float*)d_in[4];
    const float* bi     = (const float*)d_in[5];
    const float* Wu     = (const float*)d_in[6];
    const float* bu     = (const float*)d_in[7];
    const float* Wo     = (const float*)d_in[8];
    const float* bo     = (const float*)d_in[9];
    // d_in[10] = W_init: unused (c0 = 0 @ W_init.T + b_init == b_init)
    const float* b_init = (const float*)d_in[11];
    float* out = (float*)d_out;
    (void)in_sizes; (void)n_in; (void)out_size;

    zero_flags<<<1, 32>>>();
    pclstm_fused<<<Bk + NCHUNKS * Bk, 128>>>(x, y, Wf, bf, Wi, bi, Wu, bu, Wo, bo,
                                             b_init, out);
}